// round 2
// baseline (speedup 1.0000x reference)
#include <cuda_runtime.h>

#define NROI 1024
#define FH   160
#define FW   160
#define CC   256
#define CROPN 14
#define PO   7

__global__ __launch_bounds__(64) void roi_pool_kernel(
    const float* __restrict__ img,
    const float* __restrict__ rois,
    const float* __restrict__ iminfo,
    float* __restrict__ out)
{
    const int blk = blockIdx.x;            // roi * 49 + pooled position
    const int roi = blk / 49;
    const int pos = blk - roi * 49;
    const int py  = pos / PO;
    const int px  = pos - py * PO;
    const int t   = threadIdx.x;           // 0..63 -> channels [4t, 4t+3]

    // Per-ROI box math (block-uniform; recomputed per thread, cheap)
    const float rid = rois[roi * 5 + 0];
    const float rx1 = rois[roi * 5 + 1];
    const float ry1 = rois[roi * 5 + 2];
    const float rx2 = rois[roi * 5 + 3];
    const float ry2 = rois[roi * 5 + 4];
    const float imh = iminfo[roi * 2 + 0];
    const float imw = iminfo[roi * 2 + 1];
    const int   b   = (int)rid;

    // Matches reference: y = y1n*(Hf-1) + iy * ((y2n-y1n)*(Hf-1)/(ch-1))
    const float ybase = (ry1 / imh) * (float)(FH - 1);
    const float xbase = (rx1 / imw) * (float)(FW - 1);
    const float ystep = ((ry2 - ry1) / imh) * (float)(FH - 1) / (float)(CROPN - 1);
    const float xstep = ((rx2 - rx1) / imw) * (float)(FW - 1) / (float)(CROPN - 1);

    const float* imgb = img + (size_t)b * (FH * FW * CC);

    float4 best;
    best.x = -3.402823466e38f;
    best.y = -3.402823466e38f;
    best.z = -3.402823466e38f;
    best.w = -3.402823466e38f;

    #pragma unroll
    for (int dyi = 0; dyi < 2; ++dyi) {
        const int   iy = 2 * py + dyi;
        const float y  = ybase + (float)iy * ystep;
        const bool  vy = (y >= 0.0f) && (y <= (float)(FH - 1));
        const float yf = floorf(y);
        const int   yli = (int)fminf(fmaxf(yf,        0.0f), (float)(FH - 1));
        const int   yhi = (int)fminf(fmaxf(yf + 1.0f, 0.0f), (float)(FH - 1));
        const float wy  = y - yf;

        const float4* rowl = (const float4*)(imgb + (size_t)yli * (FW * CC));
        const float4* rowh = (const float4*)(imgb + (size_t)yhi * (FW * CC));

        #pragma unroll
        for (int dxi = 0; dxi < 2; ++dxi) {
            const int   ix = 2 * px + dxi;
            const float x  = xbase + (float)ix * xstep;
            const bool  vx = (x >= 0.0f) && (x <= (float)(FW - 1));
            const float xf = floorf(x);
            const int   xli = (int)fminf(fmaxf(xf,        0.0f), (float)(FW - 1));
            const int   xhi = (int)fminf(fmaxf(xf + 1.0f, 0.0f), (float)(FW - 1));
            const float wx  = x - xf;

            const float4 tl = rowl[xli * (CC / 4) + t];
            const float4 tr = rowl[xhi * (CC / 4) + t];
            const float4 bl = rowh[xli * (CC / 4) + t];
            const float4 br = rowh[xhi * (CC / 4) + t];

            float4 v;
            {
                float top, bot;
                top = tl.x + (tr.x - tl.x) * wx;
                bot = bl.x + (br.x - bl.x) * wx;
                v.x = top + (bot - top) * wy;
                top = tl.y + (tr.y - tl.y) * wx;
                bot = bl.y + (br.y - bl.y) * wx;
                v.y = top + (bot - top) * wy;
                top = tl.z + (tr.z - tl.z) * wx;
                bot = bl.z + (br.z - bl.z) * wx;
                v.z = top + (bot - top) * wy;
                top = tl.w + (tr.w - tl.w) * wx;
                bot = bl.w + (br.w - bl.w) * wx;
                v.w = top + (bot - top) * wy;
            }
            if (!(vy && vx)) { v.x = 0.0f; v.y = 0.0f; v.z = 0.0f; v.w = 0.0f; }

            best.x = fmaxf(best.x, v.x);
            best.y = fmaxf(best.y, v.y);
            best.z = fmaxf(best.z, v.z);
            best.w = fmaxf(best.w, v.w);
        }
    }

    float4* o = (float4*)(out + (size_t)blk * CC);
    o[t] = best;
}

extern "C" void kernel_launch(void* const* d_in, const int* in_sizes, int n_in,
                              void* d_out, int out_size)
{
    (void)in_sizes; (void)n_in; (void)out_size;
    const float* img    = (const float*)d_in[0];
    const float* rois   = (const float*)d_in[1];
    const float* iminfo = (const float*)d_in[2];
    float*       out    = (float*)d_out;

    roi_pool_kernel<<<NROI * 49, 64>>>(img, rois, iminfo, out);
}